// round 15
// baseline (speedup 1.0000x reference)
#include <cuda_runtime.h>
#include <cuda_fp16.h>
#include <cstdint>

// Problem constants
#define NIMG   128
#define NTOT   256
#define CCH    16
#define HP     16
#define WP     16
#define DDIM   4096          // CCH*HP*WP
#define XPTS   128           // quadrature points per dim
#define NPAIR  128           // image-pairs per dim (256/2)
#define D_PER_BLK 2
#define NBLK_MAIN  (DDIM / D_PER_BLK)   // 2048
#define NBLK_COUNT (NBLK_MAIN + 1)      // + sampler block (blockIdx 0 runs first)
#define MARGIN   4.5f
#define K2       0.72134752044448f      // 0.5*log2(e)
#define SQRT_K2  0.84932180028802f      // sqrt(K2)
#define SQRT_2PI 2.50662827463100f
#define TWO_PI   6.28318530717959f

// Scratch
__device__ float  g_Mt[DDIM * NTOT];      // pooled mean  [d][n]  (f32 truth)
__device__ float  g_Vt[DDIM * NTOT];      // pooled var   [d][n]  (f32 truth)
__device__ float4 g_stat[DDIM * 2];       // per (d,half): {minm, maxm, maxv, 0}
__device__ float4 g_grid[DDIM];           // per d: {lo, h, hw = sqrt(2pi)*h, 0}
__device__ uint2  g_ParAR[DDIM * NPAIR];  // {a2 = -m*r packed, r2 packed}
__device__ unsigned g_ParC[DDIM * NPAIR]; // c2 packed, sign = image class
__device__ double g_acc;                  // zero-init; reset each run
__device__ unsigned g_done;

__device__ __forceinline__ float rsqrt_approx(float x) {
    float y; asm("rsqrt.approx.ftz.f32 %0, %1;" : "=f"(y) : "f"(x)); return y;
}
__device__ __forceinline__ float ex2f32(float x) {
    float y; asm("ex2.approx.ftz.f32 %0, %1;" : "=f"(y) : "f"(x)); return y;
}
__device__ __forceinline__ __half2 h2ex2(__half2 x) {
    unsigned xi = *reinterpret_cast<unsigned*>(&x), yi;
    asm("ex2.approx.f16x2 %0, %1;" : "=r"(yi) : "r"(xi));
    return *reinterpret_cast<__half2*>(&yi);
}
__device__ __forceinline__ __half2 u2h(unsigned x) { return *reinterpret_cast<__half2*>(&x); }
__device__ __forceinline__ unsigned h2u(__half2 x) { return *reinterpret_cast<unsigned*>(&x); }

// ---------------------------------------------------------------------------
// Pooling + per-d stats. One block per (ph, c, half). 256 threads.
// Writes raw pooled m, v (f32, [d][n]) and per-(d,half) {minm, maxm, maxv}.
// ---------------------------------------------------------------------------
__global__ __launch_bounds__(256) void pool_kernel(
    const float* __restrict__ mu_a, const float* __restrict__ lv_a,
    const float* __restrict__ mu_b, const float* __restrict__ lv_b)
{
    const int ph  = blockIdx.x;      // 0..15
    const int c   = blockIdx.y;      // 0..15
    const int hf  = blockIdx.z;      // 0: a-rows, 1: b-rows
    const int tid = threadIdx.x;

    const float* muSrc = hf ? mu_b : mu_a;
    const float* lvSrc = hf ? lv_b : lv_a;
    const int n_off = hf * NIMG;

    __shared__ float sM[NIMG * 17];
    __shared__ float sV[NIMG * 17];
    __shared__ float sMin[16 * 17], sMax[16 * 17], sXv[16 * 17];

    const float2* mu2 = reinterpret_cast<const float2*>(muSrc);
    const float2* lv2 = reinterpret_cast<const float2*>(lvSrc);

    #pragma unroll
    for (int k = 0; k < 8; k++) {
        int o  = tid + 256 * k;      // 0..2047
        int n  = o >> 4;
        int pw = o & 15;
        int i2 = n * 8192 + c * 512 + ph * 32 + pw;
        float2 a0 = mu2[i2];
        float2 a1 = mu2[i2 + 16];
        sM[n * 17 + pw] = (a0.x + a0.y + a1.x + a1.y) * 0.25f;
        float2 b0 = lv2[i2];
        float2 b1 = lv2[i2 + 16];
        sV[n * 17 + pw] = (__expf(b0.x) + __expf(b0.y) + __expf(b1.x) + __expf(b1.y)) * 0.0625f;
    }
    __syncthreads();

    // f32 truth writes [d][n]
    const int dbase = ((c * 16 + ph) * 16) * NTOT + n_off;
    #pragma unroll
    for (int k = 0; k < 8; k++) {
        int o  = tid + 256 * k;
        int pw = o >> 7;
        int n  = o & 127;
        g_Mt[dbase + pw * NTOT + n] = sM[n * 17 + pw];
        g_Vt[dbase + pw * NTOT + n] = sV[n * 17 + pw];
    }

    // per-pw stats over the 128 n of this half
    {
        int pw = tid >> 4, ch = tid & 15;
        float mn = 1e30f, mx = -1e30f, xv = 0.f;
        #pragma unroll
        for (int q = 0; q < 8; q++) {
            int n = ch * 8 + q;
            float m = sM[n * 17 + pw];
            float v = sV[n * 17 + pw];
            mn = fminf(mn, m); mx = fmaxf(mx, m); xv = fmaxf(xv, v);
        }
        sMin[pw * 17 + ch] = mn; sMax[pw * 17 + ch] = mx; sXv[pw * 17 + ch] = xv;
    }
    __syncthreads();
    if (tid < 16) {
        float mn = 1e30f, mx = -1e30f, xv = 0.f;
        #pragma unroll
        for (int ch = 0; ch < 16; ch++) {
            mn = fminf(mn, sMin[tid * 17 + ch]);
            mx = fmaxf(mx, sMax[tid * 17 + ch]);
            xv = fmaxf(xv, sXv[tid * 17 + ch]);
        }
        int d = (c * 16 + ph) * 16 + tid;
        g_stat[d * 2 + hf] = make_float4(mn, mx, xv, 0.f);
    }
}

// ---------------------------------------------------------------------------
// Params: per-d grid (lo, h) and packed fp16 per-(i,d) params
//   a = -m*r, r = sqrt(K2/v), c = +-rsqrt(2*pi*v) (sign = image class)
// ---------------------------------------------------------------------------
__global__ __launch_bounds__(128) void params_kernel()
{
    const int d = blockIdx.x;
    const int p = threadIdx.x;   // image pair 0..127

    float4 s0 = g_stat[d * 2], s1 = g_stat[d * 2 + 1];
    float mn = fminf(s0.x, s1.x);
    float mx = fmaxf(s0.y, s1.y);
    float xv = fmaxf(s0.z, s1.z);
    float sg = sqrtf(xv);
    float lo = mn - MARGIN * sg;
    float h  = (mx + MARGIN * sg - lo) / (float)(XPTS - 1);
    if (p == 0) g_grid[d] = make_float4(lo, h, SQRT_2PI * h, 0.f);

    int n0 = 2 * p, n1 = 2 * p + 1;
    float m0 = g_Mt[d * NTOT + n0], v0 = g_Vt[d * NTOT + n0];
    float m1 = g_Mt[d * NTOT + n1], v1 = g_Vt[d * NTOT + n1];
    float r0 = SQRT_K2 * rsqrt_approx(v0);
    float r1 = SQRT_K2 * rsqrt_approx(v1);
    float c0 = rsqrt_approx(TWO_PI * v0);
    float c1 = rsqrt_approx(TWO_PI * v1);
    if (p >= 64) { c0 = -c0; c1 = -c1; }   // images 128..255: sigma = -1
    float a0 = -m0 * r0, a1 = -m1 * r1;
    g_ParAR[d * NPAIR + p] = make_uint2(h2u(__floats2half2_rn(a0, a1)),
                                        h2u(__floats2half2_rn(r0, r1)));
    g_ParC[d * NPAIR + p]  = h2u(__floats2half2_rn(c0, c1));
}

// fp16 quadrature value of one pair (i,j,d) minus the f32 closed form.
__device__ float sample_diff(int d, int i, int j)
{
    float4 gr = g_grid[d];
    uint2 ARi = g_ParAR[d * NPAIR + (i >> 1)];
    uint2 ARj = g_ParAR[d * NPAIR + (j >> 1)];
    unsigned Ci = g_ParC[d * NPAIR + (i >> 1)];
    unsigned Cj = g_ParC[d * NPAIR + (j >> 1)];

    __half ai = (i & 1) ? __high2half(u2h(ARi.x)) : __low2half(u2h(ARi.x));
    __half ri = (i & 1) ? __high2half(u2h(ARi.y)) : __low2half(u2h(ARi.y));
    __half ci = (i & 1) ? __high2half(u2h(Ci))    : __low2half(u2h(Ci));
    __half aj = (j & 1) ? __high2half(u2h(ARj.x)) : __low2half(u2h(ARj.x));
    __half rj = (j & 1) ? __high2half(u2h(ARj.y)) : __low2half(u2h(ARj.y));
    __half cj = (j & 1) ? __high2half(u2h(Cj))    : __low2half(u2h(Cj));

    __half2 a2 = __halves2half2(ai, aj);
    __half2 r2 = __halves2half2(ri, rj);
    __half2 c2 = __habs2(__halves2half2(ci, cj));  // unsigned term

    float acc = 0.f;
    #pragma unroll 4
    for (int kk = 0; kk < XPTS; kk++) {
        __half2 x2 = __float2half2_rn(gr.x + (float)kk * gr.y);
        __half2 tt = __hfma2(x2, r2, a2);
        __half2 u  = __hmul2(tt, __hneg2(tt));
        __half2 pc = __hmul2(h2ex2(u), c2);
        acc += __low2float(pc) * __high2float(pc);
    }
    float fq = gr.z * acc;

    float mi = g_Mt[d * NTOT + i], vi = g_Vt[d * NTOT + i];
    float mj = g_Mt[d * NTOT + j], vj = g_Vt[d * NTOT + j];
    float s  = vi + vj;
    float rr = rsqrt_approx(s);
    float qd = (mi - mj) * rr;
    float ft = ex2f32(-K2 * qd * qd) * rr;
    return fq - ft;
}

// ---------------------------------------------------------------------------
// Main: blockIdx 0 = bias sampler; blocks 1..2048 each do 2 dims.
// Per dim: g(x_k) = sum_i sigma_i c_i ex2(-((x-m_i) r_i)^2), accumulate
// hw * sum_k g^2.  S = sum over dims (positive sum — no cancellation blowup).
// ---------------------------------------------------------------------------
__global__ __launch_bounds__(256) void main_kernel(float* __restrict__ out)
{
    const int tid = threadIdx.x;
    __shared__ uint2    sAR[NPAIR];
    __shared__ unsigned sC[NPAIR];
    __shared__ float    sRed[XPTS * 9];
    __shared__ float    warpsum[8];

    double myC = 0.0;

    if (blockIdx.x > 0) {
        const int d2 = (int)blockIdx.x - 1;
        const int ig = tid >> 5;     // i-group 0..7 (32 images each)
        const int xs = tid & 31;     // x slot

        #pragma unroll 1
        for (int dl = 0; dl < D_PER_BLK; dl++) {
            const int d = d2 * D_PER_BLK + dl;

            if (tid < NPAIR) {
                sAR[tid] = g_ParAR[d * NPAIR + tid];
                sC[tid]  = g_ParC[d * NPAIR + tid];
            }
            const float4 gr = g_grid[d];
            __syncthreads();

            __half2 xb[4];
            #pragma unroll
            for (int t = 0; t < 4; t++)
                xb[t] = __float2half2_rn(gr.x + (float)(xs + 32 * t) * gr.y);

            __half2 hg[4];
            #pragma unroll
            for (int t = 0; t < 4; t++) hg[t] = __floats2half2_rn(0.f, 0.f);

            #pragma unroll
            for (int q = 0; q < 16; q++) {
                __half2 a2 = u2h(sAR[ig * 16 + q].x);
                __half2 r2 = u2h(sAR[ig * 16 + q].y);
                __half2 c2 = u2h(sC[ig * 16 + q]);
                #pragma unroll
                for (int t = 0; t < 4; t++) {
                    __half2 tt = __hfma2(xb[t], r2, a2);
                    __half2 u  = __hmul2(tt, __hneg2(tt));
                    hg[t] = __hfma2(h2ex2(u), c2, hg[t]);
                }
            }

            #pragma unroll
            for (int t = 0; t < 4; t++)
                sRed[(xs + 32 * t) * 9 + ig] = __low2float(hg[t]) + __high2float(hg[t]);
            __syncthreads();

            if (tid < XPTS) {
                float g = 0.f;
                #pragma unroll
                for (int k = 0; k < 8; k++) g += sRed[tid * 9 + k];
                float gsq = g * g;
                #pragma unroll
                for (int o = 16; o; o >>= 1) gsq += __shfl_xor_sync(0xffffffffu, gsq, o);
                if ((tid & 31) == 0) warpsum[tid >> 5] = gsq;
            }
            __syncthreads();
            if (tid == 0) {
                float bs = warpsum[0] + warpsum[1] + warpsum[2] + warpsum[3];
                myC += (double)gr.z * (double)bs;
            }
            __syncthreads();
        }
    } else {
        // ---- bias sampler: corrects mean quadrature + fp16 bias.
        // S_err = -256*D*bbar_od + 256*D*bbar_diag  ->  correction =
        //   +512*sum(diff_od over 2048) - 1024*sum(diff_diag over 1024)
        const int i_od = (tid * 37 + 5) & 255;   // never == tid (mod argument)
        float sum_od = 0.f, sum_dg = 0.f;
        #pragma unroll 1
        for (int k = 0; k < 8; k++) {
            int d = (tid * 331 + k * 521) & 4095;
            sum_od += sample_diff(d, i_od, tid);
        }
        #pragma unroll 1
        for (int k = 0; k < 4; k++) {
            int d = (tid * 73 + k * 1237) & 4095;
            sum_dg += sample_diff(d, tid, tid);
        }
        float v = 512.f * sum_od - 1024.f * sum_dg;
        #pragma unroll
        for (int o = 16; o; o >>= 1) v += __shfl_xor_sync(0xffffffffu, v, o);
        if ((tid & 31) == 0) warpsum[tid >> 5] = v;
        __syncthreads();
        if (tid == 0) {
            float cs = 0.f;
            #pragma unroll
            for (int k = 0; k < 8; k++) cs += warpsum[k];
            myC = (double)cs;
        }
    }

    if (tid == 0) {
        atomicAdd(&g_acc, myC);
        __threadfence();
        unsigned n = atomicAdd(&g_done, 1u);
        if (n == NBLK_COUNT - 1) {
            __threadfence();
            double total = *((volatile double*)&g_acc);
            out[0] = (float)total;
            *((volatile double*)&g_acc) = 0.0;
            *((volatile unsigned*)&g_done) = 0u;
            __threadfence();
        }
    }
}

extern "C" void kernel_launch(void* const* d_in, const int* in_sizes, int n_in,
                              void* d_out, int out_size)
{
    const float* mu_a = (const float*)d_in[0];
    const float* lv_a = (const float*)d_in[1];
    const float* mu_b = (const float*)d_in[2];
    const float* lv_b = (const float*)d_in[3];
    float* out = (float*)d_out;

    pool_kernel<<<dim3(HP, CCH, 2), 256>>>(mu_a, lv_a, mu_b, lv_b);
    params_kernel<<<DDIM, 128>>>();
    main_kernel<<<NBLK_COUNT, 256>>>(out);
}

// round 16
// speedup vs baseline: 2.4580x; 2.4580x over previous
#include <cuda_runtime.h>
#include <cuda_fp16.h>
#include <cstdint>

// Problem constants
#define NIMG   128
#define NTOT   256
#define CCH    16
#define HP     16
#define WP     16
#define DDIM   4096          // CCH*HP*WP
#define XPTS   128           // quadrature points per dim
#define NPAIR  128           // image-pairs per dim (256/2)
#define WARPS_PER_BLK 8
#define NBLK_MAIN  (DDIM / WARPS_PER_BLK)   // 512 (one dim per warp)
#define NSAMP_BLK  8
#define NBLK_COUNT (NBLK_MAIN + NSAMP_BLK)  // 520
#define MARGIN   4.5f
#define K2       0.72134752044448f      // 0.5*log2(e)
#define SQRT_K2  0.84932180028802f      // sqrt(K2)
#define SQRT_2PI 2.50662827463100f
#define TWO_PI   6.28318530717959f

// Scratch
__device__ float  g_Mt[DDIM * NTOT];      // pooled mean  [d][n]  (f32 truth)
__device__ float  g_Vt[DDIM * NTOT];      // pooled var   [d][n]  (f32 truth)
__device__ float4 g_stat[DDIM * 2];       // per (d,half): {minm, maxm, maxv, 0}
__device__ float4 g_grid[DDIM];           // per d: {lo, h, hw = sqrt(2pi)*h, 0}
__device__ uint2  g_ParAR[DDIM * NPAIR];  // {a2 = -m*r packed, r2 packed}
__device__ unsigned g_ParC[DDIM * NPAIR]; // c2 packed, sign = image class
__device__ double g_acc;                  // zero-init; reset each run
__device__ unsigned g_done;

__device__ __forceinline__ float rsqrt_approx(float x) {
    float y; asm("rsqrt.approx.ftz.f32 %0, %1;" : "=f"(y) : "f"(x)); return y;
}
__device__ __forceinline__ float ex2f32(float x) {
    float y; asm("ex2.approx.ftz.f32 %0, %1;" : "=f"(y) : "f"(x)); return y;
}
__device__ __forceinline__ __half2 h2ex2(__half2 x) {
    unsigned xi = *reinterpret_cast<unsigned*>(&x), yi;
    asm("ex2.approx.f16x2 %0, %1;" : "=r"(yi) : "r"(xi));
    return *reinterpret_cast<__half2*>(&yi);
}
__device__ __forceinline__ __half2 u2h(unsigned x) { return *reinterpret_cast<__half2*>(&x); }
__device__ __forceinline__ unsigned h2u(__half2 x) { return *reinterpret_cast<unsigned*>(&x); }

// ---------------------------------------------------------------------------
// Pooling + per-d stats. One block per (ph, c, half). 256 threads.
// ---------------------------------------------------------------------------
__global__ __launch_bounds__(256) void pool_kernel(
    const float* __restrict__ mu_a, const float* __restrict__ lv_a,
    const float* __restrict__ mu_b, const float* __restrict__ lv_b)
{
    const int ph  = blockIdx.x;      // 0..15
    const int c   = blockIdx.y;      // 0..15
    const int hf  = blockIdx.z;      // 0: a-rows, 1: b-rows
    const int tid = threadIdx.x;

    const float* muSrc = hf ? mu_b : mu_a;
    const float* lvSrc = hf ? lv_b : lv_a;
    const int n_off = hf * NIMG;

    __shared__ float sM[NIMG * 17];
    __shared__ float sV[NIMG * 17];
    __shared__ float sMin[16 * 17], sMax[16 * 17], sXv[16 * 17];

    const float2* mu2 = reinterpret_cast<const float2*>(muSrc);
    const float2* lv2 = reinterpret_cast<const float2*>(lvSrc);

    #pragma unroll
    for (int k = 0; k < 8; k++) {
        int o  = tid + 256 * k;      // 0..2047
        int n  = o >> 4;
        int pw = o & 15;
        int i2 = n * 8192 + c * 512 + ph * 32 + pw;
        float2 a0 = mu2[i2];
        float2 a1 = mu2[i2 + 16];
        sM[n * 17 + pw] = (a0.x + a0.y + a1.x + a1.y) * 0.25f;
        float2 b0 = lv2[i2];
        float2 b1 = lv2[i2 + 16];
        sV[n * 17 + pw] = (__expf(b0.x) + __expf(b0.y) + __expf(b1.x) + __expf(b1.y)) * 0.0625f;
    }
    __syncthreads();

    // f32 truth writes [d][n]
    const int dbase = ((c * 16 + ph) * 16) * NTOT + n_off;
    #pragma unroll
    for (int k = 0; k < 8; k++) {
        int o  = tid + 256 * k;
        int pw = o >> 7;
        int n  = o & 127;
        g_Mt[dbase + pw * NTOT + n] = sM[n * 17 + pw];
        g_Vt[dbase + pw * NTOT + n] = sV[n * 17 + pw];
    }

    // per-pw stats over the 128 n of this half
    {
        int pw = tid >> 4, ch = tid & 15;
        float mn = 1e30f, mx = -1e30f, xv = 0.f;
        #pragma unroll
        for (int q = 0; q < 8; q++) {
            int n = ch * 8 + q;
            float m = sM[n * 17 + pw];
            float v = sV[n * 17 + pw];
            mn = fminf(mn, m); mx = fmaxf(mx, m); xv = fmaxf(xv, v);
        }
        sMin[pw * 17 + ch] = mn; sMax[pw * 17 + ch] = mx; sXv[pw * 17 + ch] = xv;
    }
    __syncthreads();
    if (tid < 16) {
        float mn = 1e30f, mx = -1e30f, xv = 0.f;
        #pragma unroll
        for (int ch = 0; ch < 16; ch++) {
            mn = fminf(mn, sMin[tid * 17 + ch]);
            mx = fmaxf(mx, sMax[tid * 17 + ch]);
            xv = fmaxf(xv, sXv[tid * 17 + ch]);
        }
        int d = (c * 16 + ph) * 16 + tid;
        g_stat[d * 2 + hf] = make_float4(mn, mx, xv, 0.f);
    }
}

// ---------------------------------------------------------------------------
// Params: per-d grid (lo, h) and packed fp16 per-(i,d) params
//   a = -m*r, r = sqrt(K2/v), c = +-rsqrt(2*pi*v) (sign = image class)
// ---------------------------------------------------------------------------
__global__ __launch_bounds__(128) void params_kernel()
{
    const int d = blockIdx.x;
    const int p = threadIdx.x;   // image pair 0..127

    float4 s0 = g_stat[d * 2], s1 = g_stat[d * 2 + 1];
    float mn = fminf(s0.x, s1.x);
    float mx = fmaxf(s0.y, s1.y);
    float xv = fmaxf(s0.z, s1.z);
    float sg = sqrtf(xv);
    float lo = mn - MARGIN * sg;
    float h  = (mx + MARGIN * sg - lo) / (float)(XPTS - 1);
    if (p == 0) g_grid[d] = make_float4(lo, h, SQRT_2PI * h, 0.f);

    int n0 = 2 * p, n1 = 2 * p + 1;
    float m0 = g_Mt[d * NTOT + n0], v0 = g_Vt[d * NTOT + n0];
    float m1 = g_Mt[d * NTOT + n1], v1 = g_Vt[d * NTOT + n1];
    float r0 = SQRT_K2 * rsqrt_approx(v0);
    float r1 = SQRT_K2 * rsqrt_approx(v1);
    float c0 = rsqrt_approx(TWO_PI * v0);
    float c1 = rsqrt_approx(TWO_PI * v1);
    if (p >= 64) { c0 = -c0; c1 = -c1; }   // images 128..255: sigma = -1
    float a0 = -m0 * r0, a1 = -m1 * r1;
    g_ParAR[d * NPAIR + p] = make_uint2(h2u(__floats2half2_rn(a0, a1)),
                                        h2u(__floats2half2_rn(r0, r1)));
    g_ParC[d * NPAIR + p]  = h2u(__floats2half2_rn(c0, c1));
}

// fp16 quadrature value of one pair (i,j,d) minus the f32 closed form.
__device__ float sample_diff(int d, int i, int j)
{
    float4 gr = g_grid[d];
    uint2 ARi = g_ParAR[d * NPAIR + (i >> 1)];
    uint2 ARj = g_ParAR[d * NPAIR + (j >> 1)];
    unsigned Ci = g_ParC[d * NPAIR + (i >> 1)];
    unsigned Cj = g_ParC[d * NPAIR + (j >> 1)];

    __half ai = (i & 1) ? __high2half(u2h(ARi.x)) : __low2half(u2h(ARi.x));
    __half ri = (i & 1) ? __high2half(u2h(ARi.y)) : __low2half(u2h(ARi.y));
    __half ci = (i & 1) ? __high2half(u2h(Ci))    : __low2half(u2h(Ci));
    __half aj = (j & 1) ? __high2half(u2h(ARj.x)) : __low2half(u2h(ARj.x));
    __half rj = (j & 1) ? __high2half(u2h(ARj.y)) : __low2half(u2h(ARj.y));
    __half cj = (j & 1) ? __high2half(u2h(Cj))    : __low2half(u2h(Cj));

    __half2 a2 = __halves2half2(ai, aj);
    __half2 r2 = __halves2half2(ri, rj);
    __half2 c2 = __habs2(__halves2half2(ci, cj));  // unsigned term

    float acc = 0.f;
    #pragma unroll 4
    for (int kk = 0; kk < XPTS; kk++) {
        __half2 x2 = __float2half2_rn(gr.x + (float)kk * gr.y);
        __half2 tt = __hfma2(x2, r2, a2);
        __half2 u  = __hmul2(tt, __hneg2(tt));
        __half2 pc = __hmul2(h2ex2(u), c2);
        acc += __low2float(pc) * __high2float(pc);
    }
    float fq = gr.z * acc;

    float mi = g_Mt[d * NTOT + i], vi = g_Vt[d * NTOT + i];
    float mj = g_Mt[d * NTOT + j], vj = g_Vt[d * NTOT + j];
    float s  = vi + vj;
    float rr = rsqrt_approx(s);
    float qd = (mi - mj) * rr;
    float ft = ex2f32(-K2 * qd * qd) * rr;
    return fq - ft;
}

// ---------------------------------------------------------------------------
// Main: blocks 0..511 = warp-per-dim field evaluation (8 dims/block, no
// block barrier in the hot path); blocks 512..519 = distributed bias sampler.
// Per dim/warp: lane owns x-points {lane, lane+32, lane+64, lane+96};
// g(x) = sum_i sigma_i c_i ex2(-((x-m_i) r_i)^2) accumulated lane-locally,
// fp16 chains flushed to f32 every 16 pairs (32 images — same depth as the
// R15-validated path). dim contribution = hw * sum_x g^2.
// ---------------------------------------------------------------------------
__global__ __launch_bounds__(256) void main_kernel(float* __restrict__ out)
{
    const int tid  = threadIdx.x;
    const int wid  = tid >> 5;
    const int lane = tid & 31;
    __shared__ float warpsum[WARPS_PER_BLK];

    double myC = 0.0;

    if (blockIdx.x < NBLK_MAIN) {
        const int d = (int)blockIdx.x * WARPS_PER_BLK + wid;

        __shared__ uint2    sAR[WARPS_PER_BLK][NPAIR];
        __shared__ unsigned sC[WARPS_PER_BLK][NPAIR];

        // stage this dim's params (per-warp region; syncwarp suffices)
        #pragma unroll
        for (int k = 0; k < 4; k++) {
            int p = lane + 32 * k;
            sAR[wid][p] = g_ParAR[d * NPAIR + p];
            sC[wid][p]  = g_ParC[d * NPAIR + p];
        }
        const float4 gr = g_grid[d];
        __syncwarp();

        __half2 xb[4];
        #pragma unroll
        for (int t = 0; t < 4; t++)
            xb[t] = __float2half2_rn(gr.x + (float)(lane + 32 * t) * gr.y);

        float gf0 = 0.f, gf1 = 0.f, gf2 = 0.f, gf3 = 0.f;

        #pragma unroll 1
        for (int pb = 0; pb < NPAIR; pb += 16) {
            __half2 hg[4];
            #pragma unroll
            for (int t = 0; t < 4; t++) hg[t] = __floats2half2_rn(0.f, 0.f);

            #pragma unroll
            for (int p = pb; p < pb + 16; p++) {
                __half2 a2 = u2h(sAR[wid][p].x);
                __half2 r2 = u2h(sAR[wid][p].y);
                __half2 c2 = u2h(sC[wid][p]);
                #pragma unroll
                for (int t = 0; t < 4; t++) {
                    __half2 tt = __hfma2(xb[t], r2, a2);
                    __half2 u  = __hmul2(tt, __hneg2(tt));
                    hg[t] = __hfma2(h2ex2(u), c2, hg[t]);
                }
            }
            gf0 += __low2float(hg[0]) + __high2float(hg[0]);
            gf1 += __low2float(hg[1]) + __high2float(hg[1]);
            gf2 += __low2float(hg[2]) + __high2float(hg[2]);
            gf3 += __low2float(hg[3]) + __high2float(hg[3]);
        }

        float s = gf0 * gf0 + gf1 * gf1 + gf2 * gf2 + gf3 * gf3;
        #pragma unroll
        for (int o = 16; o; o >>= 1) s += __shfl_xor_sync(0xffffffffu, s, o);
        if (lane == 0) warpsum[wid] = gr.z * s;   // fold per-dim weight here
        __syncthreads();
        if (tid == 0) {
            float bs = 0.f;
            #pragma unroll
            for (int k = 0; k < WARPS_PER_BLK; k++) bs += warpsum[k];
            myC = (double)bs;
        }
    } else {
        // ---- distributed bias sampler (8 blocks x 256 threads) ----
        // totals: 2048 off-diag samples (coef 512), 1024 diag samples (coef 1024)
        const int sb = (int)blockIdx.x - NBLK_MAIN;   // 0..7
        const int gt = sb * 256 + tid;                // 0..2047

        float v = 0.f;
        {
            int d_od = (gt * 331 + 17) & 4095;
            int i_od = (gt * 37 + 5) & 255;
            int j_od = gt & 255;
            v += 512.f * sample_diff(d_od, i_od, j_od);
        }
        if (tid < 128) {
            int gd = sb * 128 + tid;                  // 0..1023
            int d_dg = (gd * 73 + 1237) & 4095;
            int i_dg = gd & 255;
            v -= 1024.f * sample_diff(d_dg, i_dg, i_dg);
        }

        #pragma unroll
        for (int o = 16; o; o >>= 1) v += __shfl_xor_sync(0xffffffffu, v, o);
        __shared__ float swsum[8];
        if (lane == 0) swsum[wid] = v;
        __syncthreads();
        if (tid == 0) {
            float cs = 0.f;
            #pragma unroll
            for (int k = 0; k < 8; k++) cs += swsum[k];
            myC = (double)cs;
        }
    }

    if (tid == 0) {
        atomicAdd(&g_acc, myC);
        __threadfence();
        unsigned n = atomicAdd(&g_done, 1u);
        if (n == NBLK_COUNT - 1) {
            __threadfence();
            double total = *((volatile double*)&g_acc);
            out[0] = (float)total;
            *((volatile double*)&g_acc) = 0.0;
            *((volatile unsigned*)&g_done) = 0u;
            __threadfence();
        }
    }
}

extern "C" void kernel_launch(void* const* d_in, const int* in_sizes, int n_in,
                              void* d_out, int out_size)
{
    const float* mu_a = (const float*)d_in[0];
    const float* lv_a = (const float*)d_in[1];
    const float* mu_b = (const float*)d_in[2];
    const float* lv_b = (const float*)d_in[3];
    float* out = (float*)d_out;

    pool_kernel<<<dim3(HP, CCH, 2), 256>>>(mu_a, lv_a, mu_b, lv_b);
    params_kernel<<<DDIM, 128>>>();
    main_kernel<<<NBLK_COUNT, 256>>>(out);
}

// round 17
// speedup vs baseline: 2.6393x; 1.0738x over previous
#include <cuda_runtime.h>
#include <cuda_fp16.h>
#include <cstdint>

// Problem constants
#define NIMG   128
#define NTOT   256
#define CCH    16
#define HP     16
#define WP     16
#define DDIM   4096          // CCH*HP*WP
#define XPTS   128           // quadrature points per dim
#define NPAIR  128           // image-pairs per dim (256/2)
#define WARPS_PER_BLK 8
#define NBLK_MAIN  (DDIM / WARPS_PER_BLK)   // 512 (one dim per warp)
#define NSAMP_BLK  8
#define NBLK_COUNT (NBLK_MAIN + NSAMP_BLK)  // 520
#define MARGIN   4.5f
#define K2       0.72134752044448f      // 0.5*log2(e)
#define SQRT_K2  0.84932180028802f      // sqrt(K2)
#define SQRT_2PI 2.50662827463100f
#define TWO_PI   6.28318530717959f

// Scratch
__device__ float  g_Mt[DDIM * NTOT];      // pooled mean  [d][n]  (f32 truth)
__device__ float  g_Vt[DDIM * NTOT];      // pooled var   [d][n]  (f32 truth)
__device__ float4 g_stat[DDIM * 2];       // per (d,half): {minm, maxm, maxv, 0}
__device__ uint2  g_ParAR[DDIM * NPAIR];  // {a2 = -m*r packed, r2 packed}
__device__ unsigned g_ParC[DDIM * NPAIR]; // c2 packed, sign = image class
__device__ double g_acc;                  // zero-init; reset each run
__device__ unsigned g_done;

__device__ __forceinline__ float rsqrt_approx(float x) {
    float y; asm("rsqrt.approx.ftz.f32 %0, %1;" : "=f"(y) : "f"(x)); return y;
}
__device__ __forceinline__ float ex2f32(float x) {
    float y; asm("ex2.approx.ftz.f32 %0, %1;" : "=f"(y) : "f"(x)); return y;
}
__device__ __forceinline__ __half2 h2ex2(__half2 x) {
    unsigned xi = *reinterpret_cast<unsigned*>(&x), yi;
    asm("ex2.approx.f16x2 %0, %1;" : "=r"(yi) : "r"(xi));
    return *reinterpret_cast<__half2*>(&yi);
}
__device__ __forceinline__ __half2 u2h(unsigned x) { return *reinterpret_cast<__half2*>(&x); }
__device__ __forceinline__ unsigned h2u(__half2 x) { return *reinterpret_cast<unsigned*>(&x); }

// Grid derivation from the two per-half stats. MUST be the single definition
// used by both the main path and the sampler so both see identical values.
__device__ __forceinline__ float3 make_grid(float4 s0, float4 s1) {
    float mn = fminf(s0.x, s1.x);
    float mx = fmaxf(s0.y, s1.y);
    float xv = fmaxf(s0.z, s1.z);
    float sg = sqrtf(xv);
    float lo = mn - MARGIN * sg;
    float h  = (mx + MARGIN * sg - lo) / (float)(XPTS - 1);
    return make_float3(lo, h, SQRT_2PI * h);
}

// ---------------------------------------------------------------------------
// Pooling + stats + packed fp16 params. One block per (ph, c, half).
// float4 input loads (one load = 2 pooled outputs). Writes:
//   - f32 truth m,v [d][n] (sampler reference)
//   - per-(d,half) stats {minm, maxm, maxv}
//   - packed fp16 params a=-m*r, r=sqrt(K2/v), c=+-rsqrt(2*pi*v)
// ---------------------------------------------------------------------------
__global__ __launch_bounds__(256) void pool_kernel(
    const float* __restrict__ mu_a, const float* __restrict__ lv_a,
    const float* __restrict__ mu_b, const float* __restrict__ lv_b)
{
    const int ph  = blockIdx.x;      // 0..15
    const int c   = blockIdx.y;      // 0..15
    const int hf  = blockIdx.z;      // 0: a-rows, 1: b-rows
    const int tid = threadIdx.x;

    const float* muSrc = hf ? mu_b : mu_a;
    const float* lvSrc = hf ? lv_b : lv_a;
    const int n_off = hf * NIMG;

    __shared__ float sM[NIMG * 17];
    __shared__ float sV[NIMG * 17];
    __shared__ float sMin[16 * 17], sMax[16 * 17], sXv[16 * 17];

    const float4* mu4 = reinterpret_cast<const float4*>(muSrc);
    const float4* lv4 = reinterpret_cast<const float4*>(lvSrc);

    // 1024 items: n (128) x pw2 (8); each item produces 2 pooled outputs.
    #pragma unroll
    for (int k = 0; k < 4; k++) {
        int o   = tid + 256 * k;     // 0..1023
        int n   = o >> 3;
        int pw2 = o & 7;
        // float4 index: n*4096 + c*256 + (2ph)*8 + pw2 ; next h-row = +8
        int i4 = n * 4096 + c * 256 + ph * 16 + pw2;
        float4 a0 = mu4[i4];
        float4 a1 = mu4[i4 + 8];
        sM[n * 17 + 2 * pw2]     = (a0.x + a0.y + a1.x + a1.y) * 0.25f;
        sM[n * 17 + 2 * pw2 + 1] = (a0.z + a0.w + a1.z + a1.w) * 0.25f;
        float4 b0 = lv4[i4];
        float4 b1 = lv4[i4 + 8];
        sV[n * 17 + 2 * pw2]     = (__expf(b0.x) + __expf(b0.y) + __expf(b1.x) + __expf(b1.y)) * 0.0625f;
        sV[n * 17 + 2 * pw2 + 1] = (__expf(b0.z) + __expf(b0.w) + __expf(b1.z) + __expf(b1.w)) * 0.0625f;
    }
    __syncthreads();

    // f32 truth writes [d][n]
    const int dbase = ((c * 16 + ph) * 16) * NTOT + n_off;
    #pragma unroll
    for (int k = 0; k < 8; k++) {
        int o  = tid + 256 * k;
        int pw = o >> 7;
        int n  = o & 127;
        g_Mt[dbase + pw * NTOT + n] = sM[n * 17 + pw];
        g_Vt[dbase + pw * NTOT + n] = sV[n * 17 + pw];
    }

    // packed fp16 params: 16 pw x 64 local-pairs per block
    const int dD = (c * 16 + ph) * 16;       // first dim of this block
    const int p_off = n_off / 2;             // pair offset (0 or 64)
    #pragma unroll
    for (int k = 0; k < 4; k++) {
        int o  = tid + 256 * k;              // 0..1023
        int pw = o >> 6;
        int q  = o & 63;                     // local pair
        float m0 = sM[(2 * q) * 17 + pw],     m1 = sM[(2 * q + 1) * 17 + pw];
        float v0 = sV[(2 * q) * 17 + pw],     v1 = sV[(2 * q + 1) * 17 + pw];
        float r0 = SQRT_K2 * rsqrt_approx(v0);
        float r1 = SQRT_K2 * rsqrt_approx(v1);
        float c0 = rsqrt_approx(TWO_PI * v0);
        float c1 = rsqrt_approx(TWO_PI * v1);
        if (hf) { c0 = -c0; c1 = -c1; }      // b-half images: sigma = -1
        float a0 = -m0 * r0, a1 = -m1 * r1;
        int idx = (dD + pw) * NPAIR + p_off + q;
        g_ParAR[idx] = make_uint2(h2u(__floats2half2_rn(a0, a1)),
                                  h2u(__floats2half2_rn(r0, r1)));
        g_ParC[idx]  = h2u(__floats2half2_rn(c0, c1));
    }

    // per-pw stats over the 128 n of this half
    {
        int pw = tid >> 4, ch = tid & 15;
        float mn = 1e30f, mx = -1e30f, xv = 0.f;
        #pragma unroll
        for (int q = 0; q < 8; q++) {
            int n = ch * 8 + q;
            float m = sM[n * 17 + pw];
            float v = sV[n * 17 + pw];
            mn = fminf(mn, m); mx = fmaxf(mx, m); xv = fmaxf(xv, v);
        }
        sMin[pw * 17 + ch] = mn; sMax[pw * 17 + ch] = mx; sXv[pw * 17 + ch] = xv;
    }
    __syncthreads();
    if (tid < 16) {
        float mn = 1e30f, mx = -1e30f, xv = 0.f;
        #pragma unroll
        for (int ch = 0; ch < 16; ch++) {
            mn = fminf(mn, sMin[tid * 17 + ch]);
            mx = fmaxf(mx, sMax[tid * 17 + ch]);
            xv = fmaxf(xv, sXv[tid * 17 + ch]);
        }
        g_stat[(dD + tid) * 2 + hf] = make_float4(mn, mx, xv, 0.f);
    }
}

// fp16 quadrature value of one pair (i,j,d) minus the f32 closed form.
__device__ float sample_diff(int d, int i, int j)
{
    float3 gr = make_grid(g_stat[d * 2], g_stat[d * 2 + 1]);
    uint2 ARi = g_ParAR[d * NPAIR + (i >> 1)];
    uint2 ARj = g_ParAR[d * NPAIR + (j >> 1)];
    unsigned Ci = g_ParC[d * NPAIR + (i >> 1)];
    unsigned Cj = g_ParC[d * NPAIR + (j >> 1)];

    __half ai = (i & 1) ? __high2half(u2h(ARi.x)) : __low2half(u2h(ARi.x));
    __half ri = (i & 1) ? __high2half(u2h(ARi.y)) : __low2half(u2h(ARi.y));
    __half ci = (i & 1) ? __high2half(u2h(Ci))    : __low2half(u2h(Ci));
    __half aj = (j & 1) ? __high2half(u2h(ARj.x)) : __low2half(u2h(ARj.x));
    __half rj = (j & 1) ? __high2half(u2h(ARj.y)) : __low2half(u2h(ARj.y));
    __half cj = (j & 1) ? __high2half(u2h(Cj))    : __low2half(u2h(Cj));

    __half2 a2 = __halves2half2(ai, aj);
    __half2 r2 = __halves2half2(ri, rj);
    __half2 c2 = __habs2(__halves2half2(ci, cj));  // unsigned term

    float acc = 0.f;
    #pragma unroll 4
    for (int kk = 0; kk < XPTS; kk++) {
        __half2 x2 = __float2half2_rn(gr.x + (float)kk * gr.y);
        __half2 tt = __hfma2(x2, r2, a2);
        __half2 u  = __hmul2(tt, __hneg2(tt));
        __half2 pc = __hmul2(h2ex2(u), c2);
        acc += __low2float(pc) * __high2float(pc);
    }
    float fq = gr.z * acc;

    float mi = g_Mt[d * NTOT + i], vi = g_Vt[d * NTOT + i];
    float mj = g_Mt[d * NTOT + j], vj = g_Vt[d * NTOT + j];
    float s  = vi + vj;
    float rr = rsqrt_approx(s);
    float qd = (mi - mj) * rr;
    float ft = ex2f32(-K2 * qd * qd) * rr;
    return fq - ft;
}

// ---------------------------------------------------------------------------
// Main: blocks 0..511 = warp-per-dim field evaluation (8 dims/block);
// blocks 512..519 = distributed bias sampler. Grid params derived inline
// from g_stat via make_grid (identical in both paths).
// ---------------------------------------------------------------------------
__global__ __launch_bounds__(256) void main_kernel(float* __restrict__ out)
{
    const int tid  = threadIdx.x;
    const int wid  = tid >> 5;
    const int lane = tid & 31;
    __shared__ float warpsum[WARPS_PER_BLK];

    double myC = 0.0;

    if (blockIdx.x < NBLK_MAIN) {
        const int d = (int)blockIdx.x * WARPS_PER_BLK + wid;

        __shared__ uint2    sAR[WARPS_PER_BLK][NPAIR];
        __shared__ unsigned sC[WARPS_PER_BLK][NPAIR];

        // stage this dim's params (per-warp region; syncwarp suffices)
        #pragma unroll
        for (int k = 0; k < 4; k++) {
            int p = lane + 32 * k;
            sAR[wid][p] = g_ParAR[d * NPAIR + p];
            sC[wid][p]  = g_ParC[d * NPAIR + p];
        }
        const float3 gr = make_grid(g_stat[d * 2], g_stat[d * 2 + 1]);
        __syncwarp();

        __half2 xb[4];
        #pragma unroll
        for (int t = 0; t < 4; t++)
            xb[t] = __float2half2_rn(gr.x + (float)(lane + 32 * t) * gr.y);

        float gf0 = 0.f, gf1 = 0.f, gf2 = 0.f, gf3 = 0.f;

        #pragma unroll 1
        for (int pb = 0; pb < NPAIR; pb += 16) {
            __half2 hg[4];
            #pragma unroll
            for (int t = 0; t < 4; t++) hg[t] = __floats2half2_rn(0.f, 0.f);

            #pragma unroll
            for (int p = pb; p < pb + 16; p++) {
                __half2 a2 = u2h(sAR[wid][p].x);
                __half2 r2 = u2h(sAR[wid][p].y);
                __half2 c2 = u2h(sC[wid][p]);
                #pragma unroll
                for (int t = 0; t < 4; t++) {
                    __half2 tt = __hfma2(xb[t], r2, a2);
                    __half2 u  = __hmul2(tt, __hneg2(tt));
                    hg[t] = __hfma2(h2ex2(u), c2, hg[t]);
                }
            }
            gf0 += __low2float(hg[0]) + __high2float(hg[0]);
            gf1 += __low2float(hg[1]) + __high2float(hg[1]);
            gf2 += __low2float(hg[2]) + __high2float(hg[2]);
            gf3 += __low2float(hg[3]) + __high2float(hg[3]);
        }

        float s = gf0 * gf0 + gf1 * gf1 + gf2 * gf2 + gf3 * gf3;
        #pragma unroll
        for (int o = 16; o; o >>= 1) s += __shfl_xor_sync(0xffffffffu, s, o);
        if (lane == 0) warpsum[wid] = gr.z * s;   // fold per-dim weight here
        __syncthreads();
        if (tid == 0) {
            float bs = 0.f;
            #pragma unroll
            for (int k = 0; k < WARPS_PER_BLK; k++) bs += warpsum[k];
            myC = (double)bs;
        }
    } else {
        // ---- distributed bias sampler (8 blocks x 256 threads) ----
        // totals: 2048 off-diag samples (coef 512), 1024 diag samples (coef 1024)
        const int sb = (int)blockIdx.x - NBLK_MAIN;   // 0..7
        const int gt = sb * 256 + tid;                // 0..2047

        float v = 0.f;
        {
            int d_od = (gt * 331 + 17) & 4095;
            int i_od = (gt * 37 + 5) & 255;
            int j_od = gt & 255;
            v += 512.f * sample_diff(d_od, i_od, j_od);
        }
        if (tid < 128) {
            int gd = sb * 128 + tid;                  // 0..1023
            int d_dg = (gd * 73 + 1237) & 4095;
            int i_dg = gd & 255;
            v -= 1024.f * sample_diff(d_dg, i_dg, i_dg);
        }

        #pragma unroll
        for (int o = 16; o; o >>= 1) v += __shfl_xor_sync(0xffffffffu, v, o);
        __shared__ float swsum[8];
        if (lane == 0) swsum[wid] = v;
        __syncthreads();
        if (tid == 0) {
            float cs = 0.f;
            #pragma unroll
            for (int k = 0; k < 8; k++) cs += swsum[k];
            myC = (double)cs;
        }
    }

    if (tid == 0) {
        atomicAdd(&g_acc, myC);
        __threadfence();
        unsigned n = atomicAdd(&g_done, 1u);
        if (n == NBLK_COUNT - 1) {
            __threadfence();
            double total = *((volatile double*)&g_acc);
            out[0] = (float)total;
            *((volatile double*)&g_acc) = 0.0;
            *((volatile unsigned*)&g_done) = 0u;
            __threadfence();
        }
    }
}

extern "C" void kernel_launch(void* const* d_in, const int* in_sizes, int n_in,
                              void* d_out, int out_size)
{
    const float* mu_a = (const float*)d_in[0];
    const float* lv_a = (const float*)d_in[1];
    const float* mu_b = (const float*)d_in[2];
    const float* lv_b = (const float*)d_in[3];
    float* out = (float*)d_out;

    pool_kernel<<<dim3(HP, CCH, 2), 256>>>(mu_a, lv_a, mu_b, lv_b);
    main_kernel<<<NBLK_COUNT, 256>>>(out);
}